// round 5
// baseline (speedup 1.0000x reference)
#include <cuda_runtime.h>
#include <cuda_bf16.h>
#include <cstdint>

// Problem constants
#define B_   8
#define S_   1024
#define DM_  512
#define H_   8
#define DK_  64
#define SP   1028   // sS row stride (pad vs 1024 to break bank alignment)

static const size_t ROWS_   = (size_t)B_ * S_;          // 8192
static const size_t LN_N_   = ROWS_ * DM_;              // 4,194,304
static const size_t ATTN_N_ = (size_t)B_*H_*S_*S_;      // 67,108,864
static const size_t MASK_N_ = (size_t)B_*S_*S_;         // 8,388,608

// ---------------- device scratch ----------------------------------------------
__device__ float g_Q  [8192*512];
__device__ float g_K  [8192*512];
__device__ float g_V  [8192*512];
__device__ float g_ctx[8192*512];
__device__ float g_pre[8192*512];
__device__ float g_attn_scratch[67108864ull];
__device__ unsigned char g_mask[8*1024*1024];
__device__ int g_mask_is_u8;

// ---------------- tf32 helpers ------------------------------------------------
__device__ __forceinline__ uint32_t f2tf(float f) {
    uint32_t r;
    asm("cvt.rna.tf32.f32 %0, %1;" : "=r"(r) : "f"(f));
    return r;
}

__device__ __forceinline__ void mma8(float* c, const uint32_t* a, uint32_t b0, uint32_t b1) {
    asm volatile("mma.sync.aligned.m16n8k8.row.col.f32.tf32.tf32.f32 "
        "{%0,%1,%2,%3}, {%4,%5,%6,%7}, {%8,%9}, {%0,%1,%2,%3};"
        : "+f"(c[0]), "+f"(c[1]), "+f"(c[2]), "+f"(c[3])
        : "r"(a[0]), "r"(a[1]), "r"(a[2]), "r"(a[3]), "r"(b0), "r"(b1));
}

// ---------------- mask dtype detection + normalization ------------------------
__global__ void mask_detect_kernel(const unsigned char* __restrict__ m) {
    __shared__ int cnt;
    if (threadIdx.x == 0) cnt = 0;
    __syncthreads();
    int local = 0;
    for (int i = threadIdx.x; i < 65536; i += 256)
        if ((i & 3) && __ldg(&m[i])) local++;
    if (local) atomicAdd(&cnt, local);
    __syncthreads();
    if (threadIdx.x == 0) g_mask_is_u8 = (cnt > 0) ? 1 : 0;
}

__global__ void mask_convert_kernel(const unsigned char* __restrict__ m) {
    const int u8 = g_mask_is_u8;
    size_t i = (size_t)blockIdx.x * blockDim.x + threadIdx.x;
    if (i < MASK_N_) {
        if (u8) g_mask[i] = (__ldg(&m[i]) != 0);
        else    g_mask[i] = (__ldg(&((const int*)m)[i]) != 0);
    }
}

// ---------------- tf32 tensor-core GEMM with register-staged prefetch ---------
// C[8192,512] = A @ B (+resid). blockIdx.z selects (A,Bm,C) triple (fused QKV).
// block tile 128x128, 8 warps of 64x32 warp tiles
__global__ __launch_bounds__(256)
void gemm_tc(const float* __restrict__ A0, const float* __restrict__ A1, const float* __restrict__ A2,
             const float* __restrict__ B0, const float* __restrict__ B1, const float* __restrict__ B2,
             const float* __restrict__ R,
             float* __restrict__ C0, float* __restrict__ C1, float* __restrict__ C2,
             int addResid)
{
    const float* A  = (blockIdx.z == 0) ? A0 : (blockIdx.z == 1) ? A1 : A2;
    const float* Bm = (blockIdx.z == 0) ? B0 : (blockIdx.z == 1) ? B1 : B2;
    float*       C  = (blockIdx.z == 0) ? C0 : (blockIdx.z == 1) ? C1 : C2;

    __shared__ uint32_t As[128 * 36];
    __shared__ uint32_t Bs[32 * 132];
    const int t = threadIdx.x;
    const int w = t >> 5, lane = t & 31, gid = lane >> 2, tid4 = lane & 3;
    const int wm = w & 1, wn = w >> 1;
    const int brow = blockIdx.y * 128, bcol = blockIdx.x * 128;

    // per-thread load coordinates (constant across k-iters)
    const int am = t >> 1, ak = (t & 1) * 4;          // wrong for 4 chunks; use loop form below
    (void)am; (void)ak;

    float acc[4][4][4];
    #pragma unroll
    for (int mt = 0; mt < 4; mt++)
        #pragma unroll
        for (int nt = 0; nt < 4; nt++)
            #pragma unroll
            for (int i = 0; i < 4; i++) acc[mt][nt][i] = 0.f;

    float4 va[4], vb[4];
    // prime k0 = 0
    #pragma unroll
    for (int i = 0; i < 4; i++) {
        int idx = i * 256 + t;
        int m = idx >> 3, k4 = (idx & 7) * 4;
        va[i] = *(const float4*)&A[(size_t)(brow + m) * 512 + k4];
        int kr = idx >> 5, nc = (idx & 31) * 4;
        vb[i] = *(const float4*)&Bm[(size_t)kr * 512 + bcol + nc];
    }

    for (int k0 = 0; k0 < 512; k0 += 32) {
        // store staged tile
        #pragma unroll
        for (int i = 0; i < 4; i++) {
            int idx = i * 256 + t;
            int m = idx >> 3, k4 = (idx & 7) * 4;
            *(uint4*)&As[m * 36 + k4] =
                make_uint4(f2tf(va[i].x), f2tf(va[i].y), f2tf(va[i].z), f2tf(va[i].w));
            int kr = idx >> 5, nc = (idx & 31) * 4;
            *(uint4*)&Bs[kr * 132 + nc] =
                make_uint4(f2tf(vb[i].x), f2tf(vb[i].y), f2tf(vb[i].z), f2tf(vb[i].w));
        }
        __syncthreads();
        // prefetch next tile (LDG overlaps the mma below)
        if (k0 + 32 < 512) {
            #pragma unroll
            for (int i = 0; i < 4; i++) {
                int idx = i * 256 + t;
                int m = idx >> 3, k4 = (idx & 7) * 4;
                va[i] = *(const float4*)&A[(size_t)(brow + m) * 512 + k0 + 32 + k4];
                int kr = idx >> 5, nc = (idx & 31) * 4;
                vb[i] = *(const float4*)&Bm[(size_t)(k0 + 32 + kr) * 512 + bcol + nc];
            }
        }
        #pragma unroll
        for (int kk = 0; kk < 4; kk++) {
            const int kb = kk * 8;
            uint32_t af[4][4];
            #pragma unroll
            for (int mt = 0; mt < 4; mt++) {
                int row = wm * 64 + mt * 16 + gid;
                af[mt][0] = As[row * 36 + kb + tid4];
                af[mt][1] = As[(row + 8) * 36 + kb + tid4];
                af[mt][2] = As[row * 36 + kb + tid4 + 4];
                af[mt][3] = As[(row + 8) * 36 + kb + tid4 + 4];
            }
            uint32_t bf[4][2];
            #pragma unroll
            for (int nt = 0; nt < 4; nt++) {
                int n = wn * 32 + nt * 8 + gid;
                bf[nt][0] = Bs[(kb + tid4) * 132 + n];
                bf[nt][1] = Bs[(kb + tid4 + 4) * 132 + n];
            }
            #pragma unroll
            for (int mt = 0; mt < 4; mt++)
                #pragma unroll
                for (int nt = 0; nt < 4; nt++)
                    mma8(acc[mt][nt], af[mt], bf[nt][0], bf[nt][1]);
        }
        __syncthreads();
    }

    #pragma unroll
    for (int mt = 0; mt < 4; mt++) {
        #pragma unroll
        for (int nt = 0; nt < 4; nt++) {
            size_t row = (size_t)(brow + wm * 64 + mt * 16 + gid);
            size_t col = (size_t)(bcol + wn * 32 + nt * 8 + 2 * tid4);
            float2 v0 = make_float2(acc[mt][nt][0], acc[mt][nt][1]);
            float2 v1 = make_float2(acc[mt][nt][2], acc[mt][nt][3]);
            if (addResid) {
                float2 r0 = *(const float2*)&R[row * 512 + col];
                float2 r1 = *(const float2*)&R[(row + 8) * 512 + col];
                v0.x += r0.x; v0.y += r0.y; v1.x += r1.x; v1.y += r1.y;
            }
            *(float2*)&C[row * 512 + col] = v0;
            *(float2*)&C[(row + 8) * 512 + col] = v1;
        }
    }
}

// ---------------- fused attention (tf32 mma, 512 threads / 16 warps) ----------
// block = (b, h, 32 q rows)
// dynamic smem: sS[32][1028] f32 + sKV[128][68] tf32 + sQ[32][68] tf32 = 175104 B
__global__ __launch_bounds__(512)
void attn_kernel(const float* __restrict__ Q, const float* __restrict__ K,
                 const float* __restrict__ V,
                 float* __restrict__ attn, float* __restrict__ ctx)
{
    extern __shared__ float sm[];
    float*    sS  = sm;                               // 32*1028 fp32 scores
    uint32_t* sKV = (uint32_t*)(sm + 32 * SP);        // 128*68 tf32
    uint32_t* sQ  = sKV + 128 * 68;                   // 32*68 tf32

    const int t = threadIdx.x;
    const int w = t >> 5, lane = t & 31, gid = lane >> 2, tid4 = lane & 3;
    const int b = blockIdx.z, h = blockIdx.y;
    const int q0 = blockIdx.x * 32;
    const size_t rowbase = (size_t)b * 1024;
    const float* Qb = Q + (rowbase + q0) * 512 + h * 64;
    const float* Kb = K + rowbase * 512 + h * 64;
    const float* Vb = V + rowbase * 512 + h * 64;

    // load Q tile 32x64 -> tf32 (512 threads: single pass)
    {
        int r = t >> 4, j = (t & 15) * 4;
        float4 v = *(const float4*)&Qb[(size_t)r * 512 + j];
        *(uint4*)&sQ[r * 68 + j] = make_uint4(f2tf(v.x), f2tf(v.y), f2tf(v.z), f2tf(v.w));
    }

    const int wm = w & 1;    // m-half (16 rows)
    const int wn = w >> 1;   // n-slice: 8 slices of 16 (phase 1) / 8 slices of 8 (phase 3)

    // ---- Phase 1: raw scores via mma into sS (warp = 16x16 tile) ----
    for (int ch = 0; ch < 8; ch++) {
        const int s0 = ch * 128;
        __syncthreads();
        #pragma unroll
        for (int p = 0; p < 4; p++) {
            int idx = p * 512 + t;
            int r = idx >> 4, j = (idx & 15) * 4;
            float4 v = *(const float4*)&Kb[(size_t)(s0 + r) * 512 + j];
            *(uint4*)&sKV[r * 68 + j] = make_uint4(f2tf(v.x), f2tf(v.y), f2tf(v.z), f2tf(v.w));
        }
        __syncthreads();
        float acc[2][4];
        #pragma unroll
        for (int nt = 0; nt < 2; nt++)
            #pragma unroll
            for (int i = 0; i < 4; i++) acc[nt][i] = 0.f;
        #pragma unroll
        for (int ks = 0; ks < 8; ks++) {
            const int k0 = ks * 8;
            uint32_t af[4];
            int arow = wm * 16 + gid;
            af[0] = sQ[arow * 68 + k0 + tid4];
            af[1] = sQ[(arow + 8) * 68 + k0 + tid4];
            af[2] = sQ[arow * 68 + k0 + tid4 + 4];
            af[3] = sQ[(arow + 8) * 68 + k0 + tid4 + 4];
            #pragma unroll
            for (int nt = 0; nt < 2; nt++) {
                int n = wn * 16 + nt * 8 + gid;
                uint32_t b0 = sKV[n * 68 + k0 + tid4];
                uint32_t b1 = sKV[n * 68 + k0 + tid4 + 4];
                mma8(acc[nt], af, b0, b1);
            }
        }
        #pragma unroll
        for (int nt = 0; nt < 2; nt++) {
            int row = wm * 16 + gid;
            int col = s0 + wn * 16 + nt * 8 + 2 * tid4;
            *(float2*)&sS[row * SP + col]       = make_float2(acc[nt][0], acc[nt][1]);
            *(float2*)&sS[(row + 8) * SP + col] = make_float2(acc[nt][2], acc[nt][3]);
        }
    }
    __syncthreads();

    // ---- Phase 2: mask + scale + exact softmax; write attn (warp = 2 rows) ----
    {
        const unsigned char* mb = g_mask + ((size_t)b * 1024 + q0) * 1024;
        #pragma unroll
        for (int ri = 0; ri < 2; ri++) {
            int r = w * 2 + ri;
            float* srow = &sS[r * SP];
            const uchar4* mrow = (const uchar4*)(mb + (size_t)r * 1024);
            float mx = -3.0e38f;
            #pragma unroll
            for (int j = 0; j < 8; j++) {
                int c4 = lane + j * 32;
                uchar4 mk = mrow[c4];
                float4 sv = *(float4*)&srow[c4 * 4];
                sv.x = mk.x ? -1e9f : sv.x * 0.125f;
                sv.y = mk.y ? -1e9f : sv.y * 0.125f;
                sv.z = mk.z ? -1e9f : sv.z * 0.125f;
                sv.w = mk.w ? -1e9f : sv.w * 0.125f;
                *(float4*)&srow[c4 * 4] = sv;
                mx = fmaxf(mx, fmaxf(fmaxf(sv.x, sv.y), fmaxf(sv.z, sv.w)));
            }
            #pragma unroll
            for (int o = 16; o > 0; o >>= 1)
                mx = fmaxf(mx, __shfl_xor_sync(0xffffffffu, mx, o));
            float l = 0.f;
            #pragma unroll
            for (int j = 0; j < 8; j++) {
                int c4 = lane + j * 32;
                float4 sv = *(float4*)&srow[c4 * 4];
                sv.x = __expf(sv.x - mx);
                sv.y = __expf(sv.y - mx);
                sv.z = __expf(sv.z - mx);
                sv.w = __expf(sv.w - mx);
                *(float4*)&srow[c4 * 4] = sv;
                l += (sv.x + sv.y) + (sv.z + sv.w);
            }
            #pragma unroll
            for (int o = 16; o > 0; o >>= 1)
                l += __shfl_xor_sync(0xffffffffu, l, o);
            float rinv = 1.0f / l;
            float* arow = attn + ((size_t)(b * 8 + h) * 1024 + q0 + r) * 1024;
            #pragma unroll
            for (int j = 0; j < 8; j++) {
                int c4 = lane + j * 32;
                float4 sv = *(float4*)&srow[c4 * 4];
                sv.x *= rinv; sv.y *= rinv; sv.z *= rinv; sv.w *= rinv;
                *(float4*)&srow[c4 * 4] = sv;
                *(float4*)&arow[c4 * 4] = sv;
            }
        }
    }

    // ---- Phase 3: ctx = P @ V via mma (warp = one 16x8 tile, full K) ----
    float acc2[4];
    acc2[0] = acc2[1] = acc2[2] = acc2[3] = 0.f;
    const int n3 = wn * 8 + gid;   // output column group

    for (int ch = 0; ch < 8; ch++) {
        const int s0 = ch * 128;
        __syncthreads();
        #pragma unroll
        for (int p = 0; p < 4; p++) {
            int idx = p * 512 + t;
            int r = idx >> 4, j = (idx & 15) * 4;
            float4 v = *(const float4*)&Vb[(size_t)(s0 + r) * 512 + j];
            *(uint4*)&sKV[r * 68 + j] = make_uint4(f2tf(v.x), f2tf(v.y), f2tf(v.z), f2tf(v.w));
        }
        __syncthreads();
        #pragma unroll
        for (int ks = 0; ks < 16; ks++) {
            const int kc = s0 + ks * 8;
            const int kl = ks * 8;
            int arow = wm * 16 + gid;
            uint32_t af[4];
            af[0] = f2tf(sS[arow * SP + kc + tid4]);
            af[1] = f2tf(sS[(arow + 8) * SP + kc + tid4]);
            af[2] = f2tf(sS[arow * SP + kc + tid4 + 4]);
            af[3] = f2tf(sS[(arow + 8) * SP + kc + tid4 + 4]);
            uint32_t b0 = sKV[(kl + tid4) * 68 + n3];
            uint32_t b1 = sKV[(kl + tid4 + 4) * 68 + n3];
            mma8(acc2, af, b0, b1);
        }
    }
    // write ctx (each warp owns a distinct 16x8 tile)
    {
        float* cb = ctx + (rowbase + q0) * 512 + h * 64;
        int row = wm * 16 + gid;
        int col = wn * 8 + 2 * tid4;
        *(float2*)&cb[(size_t)row * 512 + col]       = make_float2(acc2[0], acc2[1]);
        *(float2*)&cb[(size_t)(row + 8) * 512 + col] = make_float2(acc2[2], acc2[3]);
    }
}

// ---------------- LayerNorm over last dim (512), one row per block -----------
__global__ __launch_bounds__(128)
void ln_kernel(const float* __restrict__ X, const float* __restrict__ gamma,
               const float* __restrict__ beta, float* __restrict__ out)
{
    __shared__ float red[8];
    const int row = blockIdx.x, t = threadIdx.x;
    const float* x = X + (size_t)row * 512;
    float4 v = *(const float4*)&x[t * 4];
    float s  = (v.x + v.y) + (v.z + v.w);
    float s2 = v.x * v.x + v.y * v.y + v.z * v.z + v.w * v.w;
    #pragma unroll
    for (int o = 16; o > 0; o >>= 1) {
        s  += __shfl_xor_sync(0xffffffffu, s,  o);
        s2 += __shfl_xor_sync(0xffffffffu, s2, o);
    }
    const int warp = t >> 5, lane = t & 31;
    if (lane == 0) { red[warp] = s; red[4 + warp] = s2; }
    __syncthreads();
    s  = red[0] + red[1] + red[2] + red[3];
    s2 = red[4] + red[5] + red[6] + red[7];
    float mean = s * (1.0f / 512.0f);
    float var  = s2 * (1.0f / 512.0f) - mean * mean;
    float rstd = rsqrtf(var + 1e-5f);
    float4 gv = *(const float4*)&gamma[t * 4];
    float4 bv = *(const float4*)&beta[t * 4];
    float4 o4;
    o4.x = (v.x - mean) * rstd * gv.x + bv.x;
    o4.y = (v.y - mean) * rstd * gv.y + bv.y;
    o4.z = (v.z - mean) * rstd * gv.z + bv.z;
    o4.w = (v.w - mean) * rstd * gv.w + bv.w;
    *(float4*)&out[(size_t)row * 512 + t * 4] = o4;
}

// ---------------- launch ------------------------------------------------------
extern "C" void kernel_launch(void* const* d_in, const int* in_sizes, int n_in,
                              void* d_out, int out_size)
{
    const float* iQ   = (const float*)d_in[0];
    const float* iK   = (const float*)d_in[1];
    const float* iV   = (const float*)d_in[2];
    const unsigned char* maskRaw = (const unsigned char*)d_in[3];
    const float* WQ   = (const float*)d_in[4];
    const float* WK   = (const float*)d_in[5];
    const float* WV   = (const float*)d_in[6];
    const float* Wfc  = (const float*)d_in[7];
    const float* gam  = (const float*)d_in[8];
    const float* bet  = (const float*)d_in[9];

    float *gq, *gk, *gv, *gctx, *gpre, *gattn;
    cudaGetSymbolAddress((void**)&gq,    g_Q);
    cudaGetSymbolAddress((void**)&gk,    g_K);
    cudaGetSymbolAddress((void**)&gv,    g_V);
    cudaGetSymbolAddress((void**)&gctx,  g_ctx);
    cudaGetSymbolAddress((void**)&gpre,  g_pre);
    cudaGetSymbolAddress((void**)&gattn, g_attn_scratch);

    float* out = (float*)d_out;
    float* out_ln;
    float* out_attn;
    size_t os = (size_t)out_size;
    if (os >= LN_N_ + ATTN_N_)      { out_ln = out;   out_attn = out + LN_N_; }
    else if (os == ATTN_N_)         { out_attn = out; out_ln = gq; }
    else                            { out_ln = out;   out_attn = gattn; }

    // mask normalization (dtype-robust)
    mask_detect_kernel<<<1, 256>>>(maskRaw);
    mask_convert_kernel<<<(int)((MASK_N_ + 255) / 256), 256>>>(maskRaw);

    // fused QKV projections (one launch, grid.z selects tensor triple)
    gemm_tc<<<dim3(4, 64, 3), 256>>>(iQ, iK, iV, WQ, WK, WV, nullptr, gq, gk, gv, 0);

    // fused attention (512 threads / 16 warps)
    const int smemBytes = (32 * SP + 128 * 68 + 32 * 68) * 4;  // 175104
    cudaFuncSetAttribute(attn_kernel, cudaFuncAttributeMaxDynamicSharedMemorySize, smemBytes);
    attn_kernel<<<dim3(32, 8, 8), 512, smemBytes>>>(gq, gk, gv, out_attn, gctx);

    // output projection + residual
    gemm_tc<<<dim3(4, 64, 1), 256>>>(gctx, nullptr, nullptr, Wfc, nullptr, nullptr,
                                     iQ, gpre, nullptr, nullptr, 1);

    // layernorm
    ln_kernel<<<8192, 128>>>(gpre, gam, bet, out_ln);
}

// round 7
// speedup vs baseline: 1.0902x; 1.0902x over previous
#include <cuda_runtime.h>
#include <cuda_bf16.h>
#include <cstdint>

#define B_   8
#define S_   1024
#define DM_  512
#define H_   8
#define DK_  64
#define SP   1028   // sS row stride in words

static const size_t ROWS_   = (size_t)B_ * S_;
static const size_t LN_N_   = ROWS_ * DM_;
static const size_t ATTN_N_ = (size_t)B_*H_*S_*S_;
static const size_t MASK_N_ = (size_t)B_*S_*S_;

// ---------------- device scratch ----------------------------------------------
__device__ float g_Q  [8192*512];
__device__ float g_K  [8192*512];
__device__ float g_V  [8192*512];
__device__ float g_ctx[8192*512];
__device__ float g_pre[8192*512];
__device__ float g_attn_scratch[67108864ull];
__device__ unsigned char g_mask[8*1024*1024];
__device__ int g_mask_is_u8;

// ---------------- tf32 helpers ------------------------------------------------
__device__ __forceinline__ uint32_t f2tf(float f) {
    uint32_t r;
    asm("cvt.rna.tf32.f32 %0, %1;" : "=r"(r) : "f"(f));
    return r;
}

__device__ __forceinline__ void mma8(float* c, const uint32_t* a, uint32_t b0, uint32_t b1) {
    asm volatile("mma.sync.aligned.m16n8k8.row.col.f32.tf32.tf32.f32 "
        "{%0,%1,%2,%3}, {%4,%5,%6,%7}, {%8,%9}, {%0,%1,%2,%3};"
        : "+f"(c[0]), "+f"(c[1]), "+f"(c[2]), "+f"(c[3])
        : "r"(a[0]), "r"(a[1]), "r"(a[2]), "r"(a[3]), "r"(b0), "r"(b1));
}

// ---------------- mask dtype detection + normalization ------------------------
__global__ void mask_detect_kernel(const unsigned char* __restrict__ m) {
    __shared__ int cnt;
    if (threadIdx.x == 0) cnt = 0;
    __syncthreads();
    int local = 0;
    for (int i = threadIdx.x; i < 65536; i += 256)
        if ((i & 3) && __ldg(&m[i])) local++;
    if (local) atomicAdd(&cnt, local);
    __syncthreads();
    if (threadIdx.x == 0) g_mask_is_u8 = (cnt > 0) ? 1 : 0;
}

__global__ void mask_convert_kernel(const unsigned char* __restrict__ m) {
    const int u8 = g_mask_is_u8;
    size_t i = (size_t)blockIdx.x * blockDim.x + threadIdx.x;
    if (i < MASK_N_) {
        if (u8) g_mask[i] = (__ldg(&m[i]) != 0);
        else    g_mask[i] = (__ldg(&((const int*)m)[i]) != 0);
    }
}

// ---------------- tf32 tensor-core GEMM with register-staged prefetch ---------
__global__ __launch_bounds__(256)
void gemm_tc(const float* __restrict__ A0, const float* __restrict__ A1, const float* __restrict__ A2,
             const float* __restrict__ B0, const float* __restrict__ B1, const float* __restrict__ B2,
             const float* __restrict__ R,
             float* __restrict__ C0, float* __restrict__ C1, float* __restrict__ C2,
             int addResid)
{
    const float* A  = (blockIdx.z == 0) ? A0 : (blockIdx.z == 1) ? A1 : A2;
    const float* Bm = (blockIdx.z == 0) ? B0 : (blockIdx.z == 1) ? B1 : B2;
    float*       C  = (blockIdx.z == 0) ? C0 : (blockIdx.z == 1) ? C1 : C2;

    __shared__ uint32_t As[128 * 36];
    __shared__ uint32_t Bs[32 * 132];
    const int t = threadIdx.x;
    const int w = t >> 5, lane = t & 31, gid = lane >> 2, tid4 = lane & 3;
    const int wm = w & 1, wn = w >> 1;
    const int brow = blockIdx.y * 128, bcol = blockIdx.x * 128;

    float acc[4][4][4];
    #pragma unroll
    for (int mt = 0; mt < 4; mt++)
        #pragma unroll
        for (int nt = 0; nt < 4; nt++)
            #pragma unroll
            for (int i = 0; i < 4; i++) acc[mt][nt][i] = 0.f;

    float4 va[4], vb[4];
    #pragma unroll
    for (int i = 0; i < 4; i++) {
        int idx = i * 256 + t;
        int m = idx >> 3, k4 = (idx & 7) * 4;
        va[i] = *(const float4*)&A[(size_t)(brow + m) * 512 + k4];
        int kr = idx >> 5, nc = (idx & 31) * 4;
        vb[i] = *(const float4*)&Bm[(size_t)kr * 512 + bcol + nc];
    }

    for (int k0 = 0; k0 < 512; k0 += 32) {
        #pragma unroll
        for (int i = 0; i < 4; i++) {
            int idx = i * 256 + t;
            int m = idx >> 3, k4 = (idx & 7) * 4;
            *(uint4*)&As[m * 36 + k4] =
                make_uint4(f2tf(va[i].x), f2tf(va[i].y), f2tf(va[i].z), f2tf(va[i].w));
            int kr = idx >> 5, nc = (idx & 31) * 4;
            *(uint4*)&Bs[kr * 132 + nc] =
                make_uint4(f2tf(vb[i].x), f2tf(vb[i].y), f2tf(vb[i].z), f2tf(vb[i].w));
        }
        __syncthreads();
        if (k0 + 32 < 512) {
            #pragma unroll
            for (int i = 0; i < 4; i++) {
                int idx = i * 256 + t;
                int m = idx >> 3, k4 = (idx & 7) * 4;
                va[i] = *(const float4*)&A[(size_t)(brow + m) * 512 + k0 + 32 + k4];
                int kr = idx >> 5, nc = (idx & 31) * 4;
                vb[i] = *(const float4*)&Bm[(size_t)(k0 + 32 + kr) * 512 + bcol + nc];
            }
        }
        #pragma unroll
        for (int kk = 0; kk < 4; kk++) {
            const int kb = kk * 8;
            uint32_t af[4][4];
            #pragma unroll
            for (int mt = 0; mt < 4; mt++) {
                int row = wm * 64 + mt * 16 + gid;
                af[mt][0] = As[row * 36 + kb + tid4];
                af[mt][1] = As[(row + 8) * 36 + kb + tid4];
                af[mt][2] = As[row * 36 + kb + tid4 + 4];
                af[mt][3] = As[(row + 8) * 36 + kb + tid4 + 4];
            }
            uint32_t bf[4][2];
            #pragma unroll
            for (int nt = 0; nt < 4; nt++) {
                int n = wn * 32 + nt * 8 + gid;
                bf[nt][0] = Bs[(kb + tid4) * 132 + n];
                bf[nt][1] = Bs[(kb + tid4 + 4) * 132 + n];
            }
            #pragma unroll
            for (int mt = 0; mt < 4; mt++)
                #pragma unroll
                for (int nt = 0; nt < 4; nt++)
                    mma8(acc[mt][nt], af[mt], bf[nt][0], bf[nt][1]);
        }
        __syncthreads();
    }

    #pragma unroll
    for (int mt = 0; mt < 4; mt++) {
        #pragma unroll
        for (int nt = 0; nt < 4; nt++) {
            size_t row = (size_t)(brow + wm * 64 + mt * 16 + gid);
            size_t col = (size_t)(bcol + wn * 32 + nt * 8 + 2 * tid4);
            float2 v0 = make_float2(acc[mt][nt][0], acc[mt][nt][1]);
            float2 v1 = make_float2(acc[mt][nt][2], acc[mt][nt][3]);
            if (addResid) {
                float2 r0 = *(const float2*)&R[row * 512 + col];
                float2 r1 = *(const float2*)&R[(row + 8) * 512 + col];
                v0.x += r0.x; v0.y += r0.y; v1.x += r1.x; v1.y += r1.y;
            }
            *(float2*)&C[row * 512 + col] = v0;
            *(float2*)&C[(row + 8) * 512 + col] = v1;
        }
    }
}

// ---------------- fused attention v3: traffic-lean ----------------------------
// block = (b, h, 32 q rows), 512 threads / 16 warps
// smem: sS[32][1028] (f32 scores -> tf32 P) + sKV[256][68] tf32 + sQ[32][68] tf32
//     = 131584 + 69632 + 8704 = 209920 B
__global__ __launch_bounds__(512)
void attn_kernel(const float* __restrict__ Q, const float* __restrict__ K,
                 const float* __restrict__ V,
                 float* __restrict__ attn, float* __restrict__ ctx)
{
    extern __shared__ float sm[];
    float*    sS  = sm;                               // 32*1028
    uint32_t* sSu = (uint32_t*)sm;                    // tf32 view of sS
    uint32_t* sKV = (uint32_t*)(sm + 32 * SP);        // 256*68
    uint32_t* sQ  = sKV + 256 * 68;                   // 32*68

    const int t = threadIdx.x;
    const int w = t >> 5, lane = t & 31, gid = lane >> 2, tid4 = lane & 3;
    const int b = blockIdx.z, h = blockIdx.y;
    const int q0 = blockIdx.x * 32;
    const size_t rowbase = (size_t)b * 1024;
    const float* Qb = Q + (rowbase + q0) * 512 + h * 64;
    const float* Kb = K + rowbase * 512 + h * 64;
    const float* Vb = V + rowbase * 512 + h * 64;

    // load Q tile 32x64 -> tf32
    {
        int r = t >> 4, j = (t & 15) * 4;
        float4 v = *(const float4*)&Qb[(size_t)r * 512 + j];
        *(uint4*)&sQ[r * 68 + j] = make_uint4(f2tf(v.x), f2tf(v.y), f2tf(v.z), f2tf(v.w));
    }

    // ---- Phase 1: scores via mma, chunks of 256 kv, warp tile 16x32 (nt=4) ----
    {
        const int wm = w & 1;      // 16-row half
        const int wn = w >> 1;     // 0..7, 32-col slice
        for (int ch = 0; ch < 4; ch++) {
            const int s0 = ch * 256;
            __syncthreads();
            #pragma unroll
            for (int p = 0; p < 8; p++) {
                int idx = p * 512 + t;
                int r = idx >> 4, j = (idx & 15) * 4;
                float4 v = *(const float4*)&Kb[(size_t)(s0 + r) * 512 + j];
                *(uint4*)&sKV[r * 68 + j] = make_uint4(f2tf(v.x), f2tf(v.y), f2tf(v.z), f2tf(v.w));
            }
            __syncthreads();
            float acc[4][4];
            #pragma unroll
            for (int nt = 0; nt < 4; nt++)
                #pragma unroll
                for (int i = 0; i < 4; i++) acc[nt][i] = 0.f;
            #pragma unroll
            for (int ks = 0; ks < 8; ks++) {
                const int k0 = ks * 8;
                uint32_t af[4];
                int arow = wm * 16 + gid;
                af[0] = sQ[arow * 68 + k0 + tid4];
                af[1] = sQ[(arow + 8) * 68 + k0 + tid4];
                af[2] = sQ[arow * 68 + k0 + tid4 + 4];
                af[3] = sQ[(arow + 8) * 68 + k0 + tid4 + 4];
                #pragma unroll
                for (int nt = 0; nt < 4; nt++) {
                    int n = wn * 32 + nt * 8 + gid;
                    uint32_t b0 = sKV[n * 68 + k0 + tid4];
                    uint32_t b1 = sKV[n * 68 + k0 + tid4 + 4];
                    mma8(acc[nt], af, b0, b1);
                }
            }
            #pragma unroll
            for (int nt = 0; nt < 4; nt++) {
                int row = wm * 16 + gid;
                int col = s0 + wn * 32 + nt * 8 + 2 * tid4;
                *(float2*)&sS[row * SP + col]       = make_float2(acc[nt][0], acc[nt][1]);
                *(float2*)&sS[(row + 8) * SP + col] = make_float2(acc[nt][2], acc[nt][3]);
            }
        }
    }
    __syncthreads();

    // ---- Phase 2: register-resident softmax, 1 read + 1 tf32 write ----
    {
        const unsigned char* mb = g_mask + ((size_t)b * 1024 + q0) * 1024;
        #pragma unroll
        for (int ri = 0; ri < 2; ri++) {
            int r = w * 2 + ri;
            float* srow = &sS[r * SP];
            uint32_t* srowu = &sSu[r * SP];
            const uchar4* mrow = (const uchar4*)(mb + (size_t)r * 1024);
            float4 sv[8];
            float mx = -3.0e38f;
            #pragma unroll
            for (int j = 0; j < 8; j++) {
                int c4 = lane + j * 32;
                uchar4 mk = mrow[c4];
                float4 v = *(float4*)&srow[c4 * 4];
                v.x = mk.x ? -1e9f : v.x * 0.125f;
                v.y = mk.y ? -1e9f : v.y * 0.125f;
                v.z = mk.z ? -1e9f : v.z * 0.125f;
                v.w = mk.w ? -1e9f : v.w * 0.125f;
                sv[j] = v;
                mx = fmaxf(mx, fmaxf(fmaxf(v.x, v.y), fmaxf(v.z, v.w)));
            }
            #pragma unroll
            for (int o = 16; o > 0; o >>= 1)
                mx = fmaxf(mx, __shfl_xor_sync(0xffffffffu, mx, o));
            float l = 0.f;
            #pragma unroll
            for (int j = 0; j < 8; j++) {
                sv[j].x = __expf(sv[j].x - mx);
                sv[j].y = __expf(sv[j].y - mx);
                sv[j].z = __expf(sv[j].z - mx);
                sv[j].w = __expf(sv[j].w - mx);
                l += (sv[j].x + sv[j].y) + (sv[j].z + sv[j].w);
            }
            #pragma unroll
            for (int o = 16; o > 0; o >>= 1)
                l += __shfl_xor_sync(0xffffffffu, l, o);
            float rinv = 1.0f / l;
            float* arow = attn + ((size_t)(b * 8 + h) * 1024 + q0 + r) * 1024;
            #pragma unroll
            for (int j = 0; j < 8; j++) {
                int c4 = lane + j * 32;
                float4 v = sv[j];
                v.x *= rinv; v.y *= rinv; v.z *= rinv; v.w *= rinv;
                *(float4*)&arow[c4 * 4] = v;
                *(uint4*)&srowu[c4 * 4] =
                    make_uint4(f2tf(v.x), f2tf(v.y), f2tf(v.z), f2tf(v.w));
            }
        }
    }

    // ---- Phase 3: ctx = P @ V, warp tile 16x32 (nt=4), 4-way k-split ----
    {
        const int wm = w & 1;          // 16-row half
        const int wn = (w >> 1) & 1;   // 32-col half of 64
        const int kq = w >> 2;         // kv quarter within chunk (0..3)
        float acc2[4][4];
        #pragma unroll
        for (int nt = 0; nt < 4; nt++)
            #pragma unroll
            for (int i = 0; i < 4; i++) acc2[nt][i] = 0.f;

        for (int ch = 0; ch < 4; ch++) {
            const int s0 = ch * 256;
            __syncthreads();
            #pragma unroll
            for (int p = 0; p < 8; p++) {
                int idx = p * 512 + t;
                int r = idx >> 4, j = (idx & 15) * 4;
                float4 v = *(const float4*)&Vb[(size_t)(s0 + r) * 512 + j];
                *(uint4*)&sKV[r * 68 + j] = make_uint4(f2tf(v.x), f2tf(v.y), f2tf(v.z), f2tf(v.w));
            }
            __syncthreads();
            #pragma unroll
            for (int ks = 0; ks < 8; ks++) {
                const int kc = s0 + kq * 64 + ks * 8;   // column in sS
                const int kl = kq * 64 + ks * 8;        // row in sKV
                int arow = wm * 16 + gid;
                uint32_t af[4];
                af[0] = sSu[arow * SP + kc + tid4];
                af[1] = sSu[(arow + 8) * SP + kc + tid4];
                af[2] = sSu[arow * SP + kc + tid4 + 4];
                af[3] = sSu[(arow + 8) * SP + kc + tid4 + 4];
                #pragma unroll
                for (int nt = 0; nt < 4; nt++) {
                    int n = wn * 32 + nt * 8 + gid;
                    uint32_t b0 = sKV[(kl + tid4) * 68 + n];
                    uint32_t b1 = sKV[(kl + tid4 + 4) * 68 + n];
                    mma8(acc2[nt], af, b0, b1);
                }
            }
        }
        __syncthreads();
        // reduce 4 k-quarters: kq>0 stage partials, kq==0 combines
        float* sRed = (float*)sKV;     // 3 * 4 * 544 floats = 26112 B (fits)
        if (kq > 0) {
            int slot = ((kq - 1) * 4 + wm * 2 + wn) * 544 + lane * 17;
            #pragma unroll
            for (int nt = 0; nt < 4; nt++)
                #pragma unroll
                for (int i = 0; i < 4; i++)
                    sRed[slot + nt * 4 + i] = acc2[nt][i];
        }
        __syncthreads();
        if (kq == 0) {
            #pragma unroll
            for (int q = 1; q < 4; q++) {
                int slot = ((q - 1) * 4 + wm * 2 + wn) * 544 + lane * 17;
                #pragma unroll
                for (int nt = 0; nt < 4; nt++)
                    #pragma unroll
                    for (int i = 0; i < 4; i++)
                        acc2[nt][i] += sRed[slot + nt * 4 + i];
            }
            float* cb = ctx + (rowbase + q0) * 512 + h * 64;
            #pragma unroll
            for (int nt = 0; nt < 4; nt++) {
                int row = wm * 16 + gid;
                int col = wn * 32 + nt * 8 + 2 * tid4;
                *(float2*)&cb[(size_t)row * 512 + col]       = make_float2(acc2[nt][0], acc2[nt][1]);
                *(float2*)&cb[(size_t)(row + 8) * 512 + col] = make_float2(acc2[nt][2], acc2[nt][3]);
            }
        }
    }
}

// ---------------- LayerNorm -----------------------------------------------------
__global__ __launch_bounds__(128)
void ln_kernel(const float* __restrict__ X, const float* __restrict__ gamma,
               const float* __restrict__ beta, float* __restrict__ out)
{
    __shared__ float red[8];
    const int row = blockIdx.x, t = threadIdx.x;
    const float* x = X + (size_t)row * 512;
    float4 v = *(const float4*)&x[t * 4];
    float s  = (v.x + v.y) + (v.z + v.w);
    float s2 = v.x * v.x + v.y * v.y + v.z * v.z + v.w * v.w;
    #pragma unroll
    for (int o = 16; o > 0; o >>= 1) {
        s  += __shfl_xor_sync(0xffffffffu, s,  o);
        s2 += __shfl_xor_sync(0xffffffffu, s2, o);
    }
    const int warp = t >> 5, lane = t & 31;
    if (lane == 0) { red[warp] = s; red[4 + warp] = s2; }
    __syncthreads();
    s  = red[0] + red[1] + red[2] + red[3];
    s2 = red[4] + red[5] + red[6] + red[7];
    float mean = s * (1.0f / 512.0f);
    float var  = s2 * (1.0f / 512.0f) - mean * mean;
    float rstd = rsqrtf(var + 1e-5f);
    float4 gv = *(const float4*)&gamma[t * 4];
    float4 bv = *(const float4*)&beta[t * 4];
    float4 o4;
    o4.x = (v.x - mean) * rstd * gv.x + bv.x;
    o4.y = (v.y - mean) * rstd * gv.y + bv.y;
    o4.z = (v.z - mean) * rstd * gv.z + bv.z;
    o4.w = (v.w - mean) * rstd * gv.w + bv.w;
    *(float4*)&out[(size_t)row * 512 + t * 4] = o4;
}

// ---------------- launch ------------------------------------------------------
extern "C" void kernel_launch(void* const* d_in, const int* in_sizes, int n_in,
                              void* d_out, int out_size)
{
    const float* iQ   = (const float*)d_in[0];
    const float* iK   = (const float*)d_in[1];
    const float* iV   = (const float*)d_in[2];
    const unsigned char* maskRaw = (const unsigned char*)d_in[3];
    const float* WQ   = (const float*)d_in[4];
    const float* WK   = (const float*)d_in[5];
    const float* WV   = (const float*)d_in[6];
    const float* Wfc  = (const float*)d_in[7];
    const float* gam  = (const float*)d_in[8];
    const float* bet  = (const float*)d_in[9];

    float *gq, *gk, *gv, *gctx, *gpre, *gattn;
    cudaGetSymbolAddress((void**)&gq,    g_Q);
    cudaGetSymbolAddress((void**)&gk,    g_K);
    cudaGetSymbolAddress((void**)&gv,    g_V);
    cudaGetSymbolAddress((void**)&gctx,  g_ctx);
    cudaGetSymbolAddress((void**)&gpre,  g_pre);
    cudaGetSymbolAddress((void**)&gattn, g_attn_scratch);

    float* out = (float*)d_out;
    float* out_ln;
    float* out_attn;
    size_t os = (size_t)out_size;
    if (os >= LN_N_ + ATTN_N_)      { out_ln = out;   out_attn = out + LN_N_; }
    else if (os == ATTN_N_)         { out_attn = out; out_ln = gq; }
    else                            { out_ln = out;   out_attn = gattn; }

    mask_detect_kernel<<<1, 256>>>(maskRaw);
    mask_convert_kernel<<<(int)((MASK_N_ + 255) / 256), 256>>>(maskRaw);

    // fused QKV projections
    gemm_tc<<<dim3(4, 64, 3), 256>>>(iQ, iK, iV, WQ, WK, WV, nullptr, gq, gk, gv, 0);

    // fused attention
    const int smemBytes = (32 * SP + 256 * 68 + 32 * 68) * 4;  // 209920
    cudaFuncSetAttribute(attn_kernel, cudaFuncAttributeMaxDynamicSharedMemorySize, smemBytes);
    attn_kernel<<<dim3(32, 8, 8), 512, smemBytes>>>(gq, gk, gv, out_attn, gctx);

    // output projection + residual
    gemm_tc<<<dim3(4, 64, 1), 256>>>(gctx, nullptr, nullptr, Wfc, nullptr, nullptr,
                                     iQ, gpre, nullptr, nullptr, 1);

    ln_kernel<<<8192, 128>>>(gpre, gam, bet, out_ln);
}